// round 6
// baseline (speedup 1.0000x reference)
#include <cuda_runtime.h>

#define N_NODES 50000
#define N_EDGES 800000
#define D 128
#define K2 256   // concatenated inner dim: [mean || h]

// ---------------- scratch (no allocations allowed) ----------------
__device__ __align__(16) float g_agg[N_NODES * D];      // holds MEAN (pre-scaled)
__device__ __align__(16) float g_h0 [N_NODES * D];      // ping
__device__ __align__(16) float g_h1 [N_NODES * D];      // pong
__device__ __align__(16) float g_B  [4][K2 * D];        // per-layer [Wl^T ; Wr^T]
__device__ float g_inv[N_NODES];
__device__ int   g_deg[N_NODES];
__device__ int   g_rowptr[N_NODES + 1];
__device__ int   g_cursor[N_NODES];
__device__ int   g_eid[N_EDGES];                        // src node per CSR slot
__device__ int   g_es[N_EDGES];                         // decoded src
__device__ int   g_ed[N_EDGES];                         // decoded dst
__device__ int   g_is64;                                // dtype flag

// ---------------- dtype detection + decode ----------------
// int64 little-endian values < 2^31 have zero high words at odd int32 slots.
__global__ void detect_kernel(const int* __restrict__ e32) {
    int zeros = 0;
    for (int i = 0; i < 64; i++)
        if (e32[2 * i + 1] == 0) zeros++;
    g_is64 = (zeros == 64) ? 1 : 0;
}

__global__ void decode_kernel(const int* __restrict__ e32) {
    int i = blockIdx.x * blockDim.x + threadIdx.x;
    if (i >= 2 * N_EDGES) return;
    int v = g_is64 ? e32[2 * i] : e32[i];
    // defensive clamp: converts any residual surprise into rel_err, not a crash
    v = min(max(v, 0), N_NODES - 1);
    if (i < N_EDGES) g_es[i] = v;
    else             g_ed[i - N_EDGES] = v;
}

// ---------------- CSR build ----------------
__global__ void zero_deg_kernel() {
    int i = blockIdx.x * blockDim.x + threadIdx.x;
    if (i < N_NODES) g_deg[i] = 0;
}

__global__ void count_kernel() {
    int e = blockIdx.x * blockDim.x + threadIdx.x;
    if (e < N_EDGES) atomicAdd(&g_deg[g_ed[e]], 1);
}

// single-block exclusive scan over degrees -> rowptr, cursor, inv
__global__ void scan_kernel() {
    __shared__ int sdata[1024];
    __shared__ int carry_s;
    if (threadIdx.x == 0) carry_s = 0;
    __syncthreads();
    for (int base = 0; base < N_NODES; base += 1024) {
        int i = base + (int)threadIdx.x;
        int v = (i < N_NODES) ? g_deg[i] : 0;
        sdata[threadIdx.x] = v;
        __syncthreads();
        for (int off = 1; off < 1024; off <<= 1) {
            int t = (threadIdx.x >= off) ? sdata[threadIdx.x - off] : 0;
            __syncthreads();
            sdata[threadIdx.x] += t;
            __syncthreads();
        }
        int excl = carry_s + sdata[threadIdx.x] - v;
        if (i < N_NODES) {
            g_rowptr[i] = excl;
            g_cursor[i] = excl;
            g_inv[i]    = 1.0f / (float)max(v, 1);
        }
        __syncthreads();
        if (threadIdx.x == 1023) carry_s += sdata[1023];
        __syncthreads();
    }
    if (threadIdx.x == 0) g_rowptr[N_NODES] = carry_s;
}

__global__ void fill_kernel() {
    int e = blockIdx.x * blockDim.x + threadIdx.x;
    if (e < N_EDGES) {
        int pos = atomicAdd(&g_cursor[g_ed[e]], 1);
        g_eid[pos] = g_es[e];
    }
}

// ---------------- build transposed concat weights: B[k][j] ----------------
// out = mean @ Wl^T + h @ Wr^T  =>  B[k][j] = Wl[j][k] (k<128) else Wr[j][k-128]
__global__ void buildB_kernel(const float* __restrict__ Wl,
                              const float* __restrict__ Wr, int layer) {
    int idx = blockIdx.x * blockDim.x + threadIdx.x;
    if (idx < K2 * D) {
        int k = idx >> 7;       // 0..255
        int j = idx & 127;
        g_B[layer][idx] = (k < D) ? Wl[j * D + k] : Wr[j * D + (k - D)];
    }
}

// ---------------- gather: mean over neighbors, one warp per node ----------------
__global__ void gather_kernel(const float* __restrict__ h) {
    int warp = (blockIdx.x * blockDim.x + threadIdx.x) >> 5;
    if (warp >= N_NODES) return;
    int lane = threadIdx.x & 31;

    int beg = g_rowptr[warp];
    int end = g_rowptr[warp + 1];

    float4 acc = make_float4(0.f, 0.f, 0.f, 0.f);
    int i = beg;
    for (; i + 3 < end; i += 4) {
        int s0 = __ldg(&g_eid[i]);
        int s1 = __ldg(&g_eid[i + 1]);
        int s2 = __ldg(&g_eid[i + 2]);
        int s3 = __ldg(&g_eid[i + 3]);
        float4 v0 = *reinterpret_cast<const float4*>(h + (size_t)s0 * D + lane * 4);
        float4 v1 = *reinterpret_cast<const float4*>(h + (size_t)s1 * D + lane * 4);
        float4 v2 = *reinterpret_cast<const float4*>(h + (size_t)s2 * D + lane * 4);
        float4 v3 = *reinterpret_cast<const float4*>(h + (size_t)s3 * D + lane * 4);
        acc.x += v0.x + v1.x + v2.x + v3.x;
        acc.y += v0.y + v1.y + v2.y + v3.y;
        acc.z += v0.z + v1.z + v2.z + v3.z;
        acc.w += v0.w + v1.w + v2.w + v3.w;
    }
    for (; i < end; i++) {
        int s = __ldg(&g_eid[i]);
        float4 v = *reinterpret_cast<const float4*>(h + (size_t)s * D + lane * 4);
        acc.x += v.x; acc.y += v.y; acc.z += v.z; acc.w += v.w;
    }
    float sc = g_inv[warp];
    acc.x *= sc; acc.y *= sc; acc.z *= sc; acc.w *= sc;
    *reinterpret_cast<float4*>(g_agg + (size_t)warp * D + lane * 4) = acc;
}

// ---------------- fused GEMM: out = [mean || h] @ B + bias (opt relu) ----------------
// M=50000, N=128, K=256. Tile 128x128x32, 256 threads, 8x8 micro-tile.
__global__ void __launch_bounds__(256, 2)
gemm_kernel(const float* __restrict__ hin, int layer,
            const float* __restrict__ bias, float* __restrict__ out, int relu) {
    __shared__ float As[32][132];   // [k][row], padded (row stride 528B, 16B-aligned)
    __shared__ float Bs[32][128];   // [k][col]

    const int tid  = threadIdx.x;
    const int row0 = blockIdx.x * 128;
    const int tx = tid & 15;        // col group (8 cols)
    const int ty = tid >> 4;        // row group (8 rows)
    const float* __restrict__ Bt = g_B[layer];

    float acc[8][8];
#pragma unroll
    for (int m = 0; m < 8; m++)
#pragma unroll
        for (int n = 0; n < 8; n++) acc[m][n] = 0.f;

    for (int kt = 0; kt < 8; kt++) {
        // --- load A tile (128 rows x 32 k), transposed into As[k][row] ---
#pragma unroll
        for (int i = 0; i < 4; i++) {
            int idx = tid + i * 256;     // 0..1023
            int r   = idx >> 3;          // 0..127
            int kq  = idx & 7;           // float4 index within 32-wide k tile
            int grow = row0 + r;
            int k = kt * 32 + kq * 4;    // global k 0..255
            float4 v = make_float4(0.f, 0.f, 0.f, 0.f);
            if (grow < N_NODES) {
                if (k < D)
                    v = *reinterpret_cast<const float4*>(g_agg + (size_t)grow * D + k);
                else
                    v = *reinterpret_cast<const float4*>(hin + (size_t)grow * D + (k - D));
            }
            As[kq * 4 + 0][r] = v.x;
            As[kq * 4 + 1][r] = v.y;
            As[kq * 4 + 2][r] = v.z;
            As[kq * 4 + 3][r] = v.w;
        }
        // --- load B tile (32 k x 128 cols) ---
#pragma unroll
        for (int i = 0; i < 4; i++) {
            int idx = tid + i * 256;
            int kk  = idx >> 5;          // 0..31
            int jq  = idx & 31;          // float4 col
            float4 v = *reinterpret_cast<const float4*>(Bt + (size_t)(kt * 32 + kk) * D + jq * 4);
            *reinterpret_cast<float4*>(&Bs[kk][jq * 4]) = v;
        }
        __syncthreads();

#pragma unroll
        for (int kk = 0; kk < 32; kk++) {
            float a[8], b[8];
            float4 a0 = *reinterpret_cast<const float4*>(&As[kk][ty * 8]);
            float4 a1 = *reinterpret_cast<const float4*>(&As[kk][ty * 8 + 4]);
            float4 b0 = *reinterpret_cast<const float4*>(&Bs[kk][tx * 8]);
            float4 b1 = *reinterpret_cast<const float4*>(&Bs[kk][tx * 8 + 4]);
            a[0]=a0.x; a[1]=a0.y; a[2]=a0.z; a[3]=a0.w;
            a[4]=a1.x; a[5]=a1.y; a[6]=a1.z; a[7]=a1.w;
            b[0]=b0.x; b[1]=b0.y; b[2]=b0.z; b[3]=b0.w;
            b[4]=b1.x; b[5]=b1.y; b[6]=b1.z; b[7]=b1.w;
#pragma unroll
            for (int m = 0; m < 8; m++)
#pragma unroll
                for (int n = 0; n < 8; n++)
                    acc[m][n] += a[m] * b[n];
        }
        __syncthreads();
    }

    // --- epilogue: bias (+relu), store ---
#pragma unroll
    for (int m = 0; m < 8; m++) {
        int grow = row0 + ty * 8 + m;
        if (grow >= N_NODES) continue;
#pragma unroll
        for (int n = 0; n < 8; n += 4) {
            int j = tx * 8 + n;
            float4 r;
            r.x = acc[m][n + 0] + bias[j + 0];
            r.y = acc[m][n + 1] + bias[j + 1];
            r.z = acc[m][n + 2] + bias[j + 2];
            r.w = acc[m][n + 3] + bias[j + 3];
            if (relu) {
                r.x = fmaxf(r.x, 0.f); r.y = fmaxf(r.y, 0.f);
                r.z = fmaxf(r.z, 0.f); r.w = fmaxf(r.w, 0.f);
            }
            *reinterpret_cast<float4*>(out + (size_t)grow * D + j) = r;
        }
    }
}

// ---------------- launch ----------------
extern "C" void kernel_launch(void* const* d_in, const int* in_sizes, int n_in,
                              void* d_out, int out_size) {
    const float* x     = (const float*)d_in[0];
    const int*   e32   = (const int*)d_in[1];    // raw words; dtype detected on device
    const float* Wl[4] = {(const float*)d_in[2],  (const float*)d_in[5],
                          (const float*)d_in[8],  (const float*)d_in[11]};
    const float* bl[4] = {(const float*)d_in[3],  (const float*)d_in[6],
                          (const float*)d_in[9],  (const float*)d_in[12]};
    const float* Wr[4] = {(const float*)d_in[4],  (const float*)d_in[7],
                          (const float*)d_in[10], (const float*)d_in[13]};
    float* out = (float*)d_out;

    float* h0 = nullptr; float* h1 = nullptr;
    cudaGetSymbolAddress((void**)&h0, g_h0);
    cudaGetSymbolAddress((void**)&h1, g_h1);

    // decode edges (dtype-agnostic) + CSR build + weight prep
    detect_kernel<<<1, 1>>>(e32);
    decode_kernel<<<(2 * N_EDGES + 255) / 256, 256>>>(e32);
    zero_deg_kernel<<<(N_NODES + 255) / 256, 256>>>();
    count_kernel<<<(N_EDGES + 255) / 256, 256>>>();
    scan_kernel<<<1, 1024>>>();
    fill_kernel<<<(N_EDGES + 255) / 256, 256>>>();
    for (int l = 0; l < 4; l++)
        buildB_kernel<<<(K2 * D + 255) / 256, 256>>>(Wl[l], Wr[l], l);

    const float* hin[4]  = {x,  h0, h1, h0};
    float*       hout[4] = {h0, h1, h0, out};

    const int gather_blocks = (N_NODES * 32 + 255) / 256;
    const int gemm_blocks   = (N_NODES + 127) / 128;

    for (int l = 0; l < 4; l++) {
        gather_kernel<<<gather_blocks, 256>>>(hin[l]);
        gemm_kernel<<<gemm_blocks, 256>>>(hin[l], l, bl[l], hout[l], l == 0 ? 1 : 0);
    }
}

// round 11
// speedup vs baseline: 1.3874x; 1.3874x over previous
#include <cuda_runtime.h>
#include <cuda_bf16.h>
#include <cstdint>

#define N_NODES 50000
#define N_EDGES 800000
#define D 128
#define K2 256   // concatenated inner dim: [mean || h]

// ---------------- scratch (no allocations allowed) ----------------
__device__ __align__(16) float g_agg[N_NODES * D];      // MEAN (pre-scaled)
__device__ __align__(16) float g_h0 [N_NODES * D];      // ping
__device__ __align__(16) float g_h1 [N_NODES * D];      // pong
__device__ __align__(16) __nv_bfloat16 g_Wbh[4][D * K2]; // B operand hi, [j][k] K-major
__device__ __align__(16) __nv_bfloat16 g_Wbl[4][D * K2]; // B operand lo
__device__ float g_inv[N_NODES];
__device__ int   g_deg[N_NODES];
__device__ int   g_rowptr[N_NODES + 1];
__device__ int   g_cursor[N_NODES];
__device__ int   g_eid[N_EDGES];
__device__ int   g_es[N_EDGES];
__device__ int   g_ed[N_EDGES];
__device__ int   g_is64;

// ---------------- helpers ----------------
__device__ __forceinline__ uint32_t smem_to_u32(const void* p) {
    uint32_t a;
    asm("{ .reg .u64 t; cvta.to.shared.u64 t, %1; cvt.u32.u64 %0, t; }" : "=r"(a) : "l"(p));
    return a;
}
#define SMEM_SWIZZLE_128B(o) ((o) ^ (((o) >> 3) & 0x70))

#define LDMATRIX_X4(r0, r1, r2, r3, addr) \
    asm volatile("ldmatrix.sync.aligned.m8n8.x4.shared.b16 {%0,%1,%2,%3}, [%4];" \
                 : "=r"(r0), "=r"(r1), "=r"(r2), "=r"(r3) : "r"(addr))

#define MMA_BF16(d0, d1, d2, d3, a0, a1, a2, a3, b0, b1) \
    asm volatile("mma.sync.aligned.m16n8k16.row.col.f32.bf16.bf16.f32 " \
                 "{%0,%1,%2,%3}, {%4,%5,%6,%7}, {%8,%9}, {%0,%1,%2,%3};" \
                 : "+f"(d0), "+f"(d1), "+f"(d2), "+f"(d3) \
                 : "r"(a0), "r"(a1), "r"(a2), "r"(a3), "r"(b0), "r"(b1))

// ---------------- dtype detection + decode ----------------
__global__ void detect_kernel(const int* __restrict__ e32) {
    int zeros = 0;
    for (int i = 0; i < 64; i++)
        if (e32[2 * i + 1] == 0) zeros++;
    g_is64 = (zeros == 64) ? 1 : 0;
}

__global__ void decode_kernel(const int* __restrict__ e32) {
    int i = blockIdx.x * blockDim.x + threadIdx.x;
    if (i >= 2 * N_EDGES) return;
    int v = g_is64 ? e32[2 * i] : e32[i];
    v = min(max(v, 0), N_NODES - 1);
    if (i < N_EDGES) g_es[i] = v;
    else             g_ed[i - N_EDGES] = v;
}

// ---------------- CSR build ----------------
__global__ void zero_deg_kernel() {
    int i = blockIdx.x * blockDim.x + threadIdx.x;
    if (i < N_NODES) g_deg[i] = 0;
}

__global__ void count_kernel() {
    int e = blockIdx.x * blockDim.x + threadIdx.x;
    if (e < N_EDGES) atomicAdd(&g_deg[g_ed[e]], 1);
}

__global__ void scan_kernel() {
    __shared__ int sdata[1024];
    __shared__ int carry_s;
    if (threadIdx.x == 0) carry_s = 0;
    __syncthreads();
    for (int base = 0; base < N_NODES; base += 1024) {
        int i = base + (int)threadIdx.x;
        int v = (i < N_NODES) ? g_deg[i] : 0;
        sdata[threadIdx.x] = v;
        __syncthreads();
        for (int off = 1; off < 1024; off <<= 1) {
            int t = (threadIdx.x >= off) ? sdata[threadIdx.x - off] : 0;
            __syncthreads();
            sdata[threadIdx.x] += t;
            __syncthreads();
        }
        int excl = carry_s + sdata[threadIdx.x] - v;
        if (i < N_NODES) {
            g_rowptr[i] = excl;
            g_cursor[i] = excl;
            g_inv[i]    = 1.0f / (float)max(v, 1);
        }
        __syncthreads();
        if (threadIdx.x == 1023) carry_s += sdata[1023];
        __syncthreads();
    }
    if (threadIdx.x == 0) g_rowptr[N_NODES] = carry_s;
}

__global__ void fill_kernel() {
    int e = blockIdx.x * blockDim.x + threadIdx.x;
    if (e < N_EDGES) {
        int pos = atomicAdd(&g_cursor[g_ed[e]], 1);
        g_eid[pos] = g_es[e];
    }
}

// ---------------- build bf16 hi/lo weights, [j][k] K-major ----------------
__global__ void buildWb_kernel(const float* __restrict__ Wl,
                               const float* __restrict__ Wr, int layer) {
    int idx = blockIdx.x * blockDim.x + threadIdx.x;
    if (idx < D * K2) {
        int j = idx >> 8;        // 0..127
        int k = idx & 255;       // 0..255
        float w = (k < D) ? Wl[j * D + k] : Wr[j * D + (k - D)];
        __nv_bfloat16 hi = __float2bfloat16(w);
        __nv_bfloat16 lo = __float2bfloat16(w - __bfloat162float(hi));
        g_Wbh[layer][idx] = hi;
        g_Wbl[layer][idx] = lo;
    }
}

// ---------------- gather: mean over neighbors, one warp per node ----------------
__global__ void gather_kernel(const float* __restrict__ h) {
    int warp = (blockIdx.x * blockDim.x + threadIdx.x) >> 5;
    if (warp >= N_NODES) return;
    int lane = threadIdx.x & 31;

    int beg = g_rowptr[warp];
    int end = g_rowptr[warp + 1];

    float4 acc = make_float4(0.f, 0.f, 0.f, 0.f);
    int i = beg;
    for (; i + 3 < end; i += 4) {
        int s0 = __ldg(&g_eid[i]);
        int s1 = __ldg(&g_eid[i + 1]);
        int s2 = __ldg(&g_eid[i + 2]);
        int s3 = __ldg(&g_eid[i + 3]);
        float4 v0 = *reinterpret_cast<const float4*>(h + (size_t)s0 * D + lane * 4);
        float4 v1 = *reinterpret_cast<const float4*>(h + (size_t)s1 * D + lane * 4);
        float4 v2 = *reinterpret_cast<const float4*>(h + (size_t)s2 * D + lane * 4);
        float4 v3 = *reinterpret_cast<const float4*>(h + (size_t)s3 * D + lane * 4);
        acc.x += v0.x + v1.x + v2.x + v3.x;
        acc.y += v0.y + v1.y + v2.y + v3.y;
        acc.z += v0.z + v1.z + v2.z + v3.z;
        acc.w += v0.w + v1.w + v2.w + v3.w;
    }
    for (; i < end; i++) {
        int s = __ldg(&g_eid[i]);
        float4 v = *reinterpret_cast<const float4*>(h + (size_t)s * D + lane * 4);
        acc.x += v.x; acc.y += v.y; acc.z += v.z; acc.w += v.w;
    }
    float sc = g_inv[warp];
    acc.x *= sc; acc.y *= sc; acc.z *= sc; acc.w *= sc;
    *reinterpret_cast<float4*>(g_agg + (size_t)warp * D + lane * 4) = acc;
}

// ---------------- HMMA GEMM: out = [mean || h] @ Bop^T + bias (opt relu) -------
// CTA: 256 thr (8 warps, 2x4), tile M=128 N=128, K=256 in 4 chunks of 64.
// Split-bf16: acc += Ah*Bh + Ah*Bl + Al*Bh (fp32 acc in registers).
#define OFF_AH 0
#define OFF_AL 16384
#define OFF_BH 32768
#define OFF_BL 49152
#define SMEM_TOT 65536

__global__ void __launch_bounds__(256, 2)
hmma_gemm_kernel(const float* __restrict__ hin, int layer,
                 const float* __restrict__ bias, float* __restrict__ out, int relu) {
    extern __shared__ char smem[];
    const uint32_t smem_base = smem_to_u32(smem);
    const int tid  = threadIdx.x;
    const int wid  = tid >> 5;
    const int lane = tid & 31;
    const int row0 = blockIdx.x * 128;
    const int warp_m = (wid >> 2) * 64;   // 0 | 64
    const int warp_n = (wid & 3) * 32;    // 0,32,64,96

    const __nv_bfloat16* __restrict__ Bhp = g_Wbh[layer];
    const __nv_bfloat16* __restrict__ Blp = g_Wbl[layer];

    float acc[4][4][4];
#pragma unroll
    for (int mt = 0; mt < 4; mt++)
#pragma unroll
        for (int nt = 0; nt < 4; nt++)
#pragma unroll
            for (int q = 0; q < 4; q++) acc[mt][nt][q] = 0.f;

    // precomputed ldmatrix lane-address offsets (within a 128-row x 128B tile)
    const int a_row  = (lane & 15);
    const int a_koff = (lane >> 4) * 8;
    const int b_row  = (lane & 7) + ((lane >> 4) << 3);
    const int b_koff = ((lane >> 3) & 1) * 8;

    for (int chunk = 0; chunk < 4; chunk++) {
        // --- A chunk: 128 rows x 64 bf16 (hi & lo) from fp32 [mean||h] ---
#pragma unroll
        for (int i = 0; i < 8; i++) {
            int g  = tid + i * 256;       // 0..2047
            int r  = g >> 4;              // row 0..127
            int c4 = g & 15;              // group of 4 bf16
            int grow = row0 + r;
            int k = chunk * 64 + c4 * 4;
            float4 v = make_float4(0.f, 0.f, 0.f, 0.f);
            if (grow < N_NODES) {
                v = (k < D)
                  ? *reinterpret_cast<const float4*>(g_agg + (size_t)grow * D + k)
                  : *reinterpret_cast<const float4*>(hin   + (size_t)grow * D + (k - D));
            }
            __nv_bfloat16 h0 = __float2bfloat16(v.x), h1 = __float2bfloat16(v.y);
            __nv_bfloat16 h2 = __float2bfloat16(v.z), h3 = __float2bfloat16(v.w);
            __nv_bfloat16 l0 = __float2bfloat16(v.x - __bfloat162float(h0));
            __nv_bfloat16 l1 = __float2bfloat16(v.y - __bfloat162float(h1));
            __nv_bfloat16 l2 = __float2bfloat16(v.z - __bfloat162float(h2));
            __nv_bfloat16 l3 = __float2bfloat16(v.w - __bfloat162float(h3));
            uint32_t sw = SMEM_SWIZZLE_128B((uint32_t)(r * 128 + c4 * 8));
            uint2 ph, pl;
            ph.x = ((uint32_t)__bfloat16_as_ushort(h1) << 16) | __bfloat16_as_ushort(h0);
            ph.y = ((uint32_t)__bfloat16_as_ushort(h3) << 16) | __bfloat16_as_ushort(h2);
            pl.x = ((uint32_t)__bfloat16_as_ushort(l1) << 16) | __bfloat16_as_ushort(l0);
            pl.y = ((uint32_t)__bfloat16_as_ushort(l3) << 16) | __bfloat16_as_ushort(l2);
            *reinterpret_cast<uint2*>(smem + OFF_AH + sw) = ph;
            *reinterpret_cast<uint2*>(smem + OFF_AL + sw) = pl;
        }
        // --- B chunk: 128 n-rows x 64 bf16 (hi & lo), bf16 in gmem ---
#pragma unroll
        for (int i = 0; i < 8; i++) {
            int g  = tid + i * 256;
            int r  = g >> 4;
            int c4 = g & 15;
            int k = chunk * 64 + c4 * 4;
            uint2 vh = *reinterpret_cast<const uint2*>(Bhp + (size_t)r * K2 + k);
            uint2 vl = *reinterpret_cast<const uint2*>(Blp + (size_t)r * K2 + k);
            uint32_t sw = SMEM_SWIZZLE_128B((uint32_t)(r * 128 + c4 * 8));
            *reinterpret_cast<uint2*>(smem + OFF_BH + sw) = vh;
            *reinterpret_cast<uint2*>(smem + OFF_BL + sw) = vl;
        }
        __syncthreads();

#pragma unroll
        for (int ks = 0; ks < 4; ks++) {
            // B fragments: hi and lo, 2 x4-loads each (covers 32 n x 16 k)
            uint32_t bh[2][4], blo[2][4];
#pragma unroll
            for (int np = 0; np < 2; np++) {
                uint32_t off = SMEM_SWIZZLE_128B(
                    (uint32_t)((warp_n + np * 16 + b_row) * 128 + (ks * 16 + b_koff) * 2));
                LDMATRIX_X4(bh[np][0], bh[np][1], bh[np][2], bh[np][3],
                            smem_base + OFF_BH + off);
                LDMATRIX_X4(blo[np][0], blo[np][1], blo[np][2], blo[np][3],
                            smem_base + OFF_BL + off);
            }
            // A hi fragments, then hi*hi + hi*lo
            uint32_t a[4][4];
#pragma unroll
            for (int mt = 0; mt < 4; mt++) {
                uint32_t off = SMEM_SWIZZLE_128B(
                    (uint32_t)((warp_m + mt * 16 + a_row) * 128 + (ks * 16 + a_koff) * 2));
                LDMATRIX_X4(a[mt][0], a[mt][1], a[mt][2], a[mt][3],
                            smem_base + OFF_AH + off);
            }
#pragma unroll
            for (int mt = 0; mt < 4; mt++)
#pragma unroll
                for (int nt = 0; nt < 4; nt++) {
                    int np = nt >> 1, hf = nt & 1;
                    MMA_BF16(acc[mt][nt][0], acc[mt][nt][1], acc[mt][nt][2], acc[mt][nt][3],
                             a[mt][0], a[mt][1], a[mt][2], a[mt][3],
                             bh[np][hf * 2], bh[np][hf * 2 + 1]);
                    MMA_BF16(acc[mt][nt][0], acc[mt][nt][1], acc[mt][nt][2], acc[mt][nt][3],
                             a[mt][0], a[mt][1], a[mt][2], a[mt][3],
                             blo[np][hf * 2], blo[np][hf * 2 + 1]);
                }
            // A lo fragments (overwrite), then lo*hi
#pragma unroll
            for (int mt = 0; mt < 4; mt++) {
                uint32_t off = SMEM_SWIZZLE_128B(
                    (uint32_t)((warp_m + mt * 16 + a_row) * 128 + (ks * 16 + a_koff) * 2));
                LDMATRIX_X4(a[mt][0], a[mt][1], a[mt][2], a[mt][3],
                            smem_base + OFF_AL + off);
            }
#pragma unroll
            for (int mt = 0; mt < 4; mt++)
#pragma unroll
                for (int nt = 0; nt < 4; nt++) {
                    int np = nt >> 1, hf = nt & 1;
                    MMA_BF16(acc[mt][nt][0], acc[mt][nt][1], acc[mt][nt][2], acc[mt][nt][3],
                             a[mt][0], a[mt][1], a[mt][2], a[mt][3],
                             bh[np][hf * 2], bh[np][hf * 2 + 1]);
                }
        }
        __syncthreads();
    }

    // --- epilogue: bias (+relu), store fp32 ---
    const int gid = lane >> 2;   // groupID (row within tile)
    const int tig = lane & 3;    // thread in group (col pair)
#pragma unroll
    for (int mt = 0; mt < 4; mt++) {
        int r_base = row0 + warp_m + mt * 16 + gid;
#pragma unroll
        for (int nt = 0; nt < 4; nt++) {
            int j = warp_n + nt * 8 + tig * 2;
            float b0 = __ldg(&bias[j]), b1 = __ldg(&bias[j + 1]);
            float2 v0, v1;
            v0.x = acc[mt][nt][0] + b0; v0.y = acc[mt][nt][1] + b1;
            v1.x = acc[mt][nt][2] + b0; v1.y = acc[mt][nt][3] + b1;
            if (relu) {
                v0.x = fmaxf(v0.x, 0.f); v0.y = fmaxf(v0.y, 0.f);
                v1.x = fmaxf(v1.x, 0.f); v1.y = fmaxf(v1.y, 0.f);
            }
            if (r_base < N_NODES)
                *reinterpret_cast<float2*>(out + (size_t)r_base * D + j) = v0;
            if (r_base + 8 < N_NODES)
                *reinterpret_cast<float2*>(out + (size_t)(r_base + 8) * D + j) = v1;
        }
    }
}

// ---------------- launch ----------------
extern "C" void kernel_launch(void* const* d_in, const int* in_sizes, int n_in,
                              void* d_out, int out_size) {
    const float* x     = (const float*)d_in[0];
    const int*   e32   = (const int*)d_in[1];
    const float* Wl[4] = {(const float*)d_in[2],  (const float*)d_in[5],
                          (const float*)d_in[8],  (const float*)d_in[11]};
    const float* bl[4] = {(const float*)d_in[3],  (const float*)d_in[6],
                          (const float*)d_in[9],  (const float*)d_in[12]};
    const float* Wr[4] = {(const float*)d_in[4],  (const float*)d_in[7],
                          (const float*)d_in[10], (const float*)d_in[13]};
    float* out = (float*)d_out;

    float* h0 = nullptr; float* h1 = nullptr;
    cudaGetSymbolAddress((void**)&h0, g_h0);
    cudaGetSymbolAddress((void**)&h1, g_h1);

    cudaFuncSetAttribute(hmma_gemm_kernel,
                         cudaFuncAttributeMaxDynamicSharedMemorySize, SMEM_TOT);

    // decode edges + CSR build + weight prep
    detect_kernel<<<1, 1>>>(e32);
    decode_kernel<<<(2 * N_EDGES + 255) / 256, 256>>>(e32);
    zero_deg_kernel<<<(N_NODES + 255) / 256, 256>>>();
    count_kernel<<<(N_EDGES + 255) / 256, 256>>>();
    scan_kernel<<<1, 1024>>>();
    fill_kernel<<<(N_EDGES + 255) / 256, 256>>>();
    for (int l = 0; l < 4; l++)
        buildWb_kernel<<<(D * K2 + 255) / 256, 256>>>(Wl[l], Wr[l], l);

    const float* hin[4]  = {x,  h0, h1, h0};
    float*       hout[4] = {h0, h1, h0, out};

    const int gather_blocks = (N_NODES * 32 + 255) / 256;
    const int gemm_blocks   = (N_NODES + 127) / 128;   // 391

    for (int l = 0; l < 4; l++) {
        gather_kernel<<<gather_blocks, 256>>>(hin[l]);
        hmma_gemm_kernel<<<gemm_blocks, 256, SMEM_TOT>>>(hin[l], l, bl[l], hout[l], l == 0 ? 1 : 0);
    }
}

// round 13
// speedup vs baseline: 1.4314x; 1.0317x over previous
#include <cuda_runtime.h>
#include <cuda_bf16.h>
#include <cstdint>

#define N_NODES 50000
#define N_EDGES 800000
#define D 128
#define K2 256   // concatenated inner dim: [mean || h]
#define SCAN_BLOCKS 49   // ceil(50000/1024)

// ---------------- scratch (no allocations allowed) ----------------
__device__ __align__(16) float g_h0 [N_NODES * D];      // ping
__device__ __align__(16) float g_h1 [N_NODES * D];      // pong
__device__ __align__(16) __nv_bfloat16 g_Wbh[4][D * K2]; // B operand hi, [j][k] K-major
__device__ __align__(16) __nv_bfloat16 g_Wbl[4][D * K2]; // B operand lo
__device__ int   g_deg[N_NODES];
__device__ int   g_rowptr[N_NODES + 1];
__device__ int   g_cursor[N_NODES];
__device__ int   g_eid[N_EDGES];
__device__ int   g_es[N_EDGES];
__device__ int   g_ed[N_EDGES];
__device__ int   g_bsum[SCAN_BLOCKS];
__device__ int   g_is64;

// ---------------- helpers ----------------
__device__ __forceinline__ uint32_t smem_to_u32(const void* p) {
    uint32_t a;
    asm("{ .reg .u64 t; cvta.to.shared.u64 t, %1; cvt.u32.u64 %0, t; }" : "=r"(a) : "l"(p));
    return a;
}
#define SMEM_SWIZZLE_128B(o) ((o) ^ (((o) >> 3) & 0x70))

#define LDMATRIX_X4(r0, r1, r2, r3, addr) \
    asm volatile("ldmatrix.sync.aligned.m8n8.x4.shared.b16 {%0,%1,%2,%3}, [%4];" \
                 : "=r"(r0), "=r"(r1), "=r"(r2), "=r"(r3) : "r"(addr))

#define MMA_BF16(d0, d1, d2, d3, a0, a1, a2, a3, b0, b1) \
    asm volatile("mma.sync.aligned.m16n8k16.row.col.f32.bf16.bf16.f32 " \
                 "{%0,%1,%2,%3}, {%4,%5,%6,%7}, {%8,%9}, {%0,%1,%2,%3};" \
                 : "+f"(d0), "+f"(d1), "+f"(d2), "+f"(d3) \
                 : "r"(a0), "r"(a1), "r"(a2), "r"(a3), "r"(b0), "r"(b1))

// ---------------- dtype detection + decode ----------------
__global__ void detect_kernel(const int* __restrict__ e32) {
    bool z = (e32[2 * threadIdx.x + 1] == 0);
    unsigned m = __ballot_sync(0xffffffffu, z);
    if (threadIdx.x == 0) g_is64 = (m == 0xffffffffu) ? 1 : 0;
}

__global__ void decode_kernel(const int* __restrict__ e32) {
    int i = blockIdx.x * blockDim.x + threadIdx.x;
    if (i >= 2 * N_EDGES) return;
    int v = g_is64 ? e32[2 * i] : e32[i];
    v = min(max(v, 0), N_NODES - 1);
    if (i < N_EDGES) g_es[i] = v;
    else             g_ed[i - N_EDGES] = v;
}

// ---------------- CSR build ----------------
__global__ void zero_deg_kernel() {
    int i = blockIdx.x * blockDim.x + threadIdx.x;
    if (i < N_NODES) g_deg[i] = 0;
}

__global__ void count_kernel() {
    int e = blockIdx.x * blockDim.x + threadIdx.x;
    if (e < N_EDGES) atomicAdd(&g_deg[g_ed[e]], 1);
}

// scan1: per-block exclusive scan (1024 nodes/block), block totals to g_bsum
__global__ void scan1_kernel() {
    __shared__ int wsum[32];
    int i = blockIdx.x * 1024 + threadIdx.x;
    int lane = threadIdx.x & 31, wrp = threadIdx.x >> 5;
    int v = (i < N_NODES) ? g_deg[i] : 0;
    int x = v;
#pragma unroll
    for (int off = 1; off < 32; off <<= 1) {
        int y = __shfl_up_sync(0xffffffffu, x, off);
        if (lane >= off) x += y;
    }
    if (lane == 31) wsum[wrp] = x;
    __syncthreads();
    if (wrp == 0) {
        int s = wsum[lane];
#pragma unroll
        for (int off = 1; off < 32; off <<= 1) {
            int y = __shfl_up_sync(0xffffffffu, s, off);
            if (lane >= off) s += y;
        }
        wsum[lane] = s;
    }
    __syncthreads();
    int incl = x + (wrp > 0 ? wsum[wrp - 1] : 0);
    if (i < N_NODES) g_rowptr[i] = incl - v;       // block-local exclusive
    if (threadIdx.x == 1023) g_bsum[blockIdx.x] = incl;
}

// scan2: exclusive scan of SCAN_BLOCKS block totals (64 threads, 2 warps)
__global__ void scan2_kernel() {
    __shared__ int ws[2];
    int t = threadIdx.x;                 // 0..63
    int lane = t & 31, wrp = t >> 5;
    int v = (t < SCAN_BLOCKS) ? g_bsum[t] : 0;
    int x = v;
#pragma unroll
    for (int off = 1; off < 32; off <<= 1) {
        int y = __shfl_up_sync(0xffffffffu, x, off);
        if (lane >= off) x += y;
    }
    if (lane == 31) ws[wrp] = x;
    __syncthreads();
    int excl = x - v + (wrp == 1 ? ws[0] : 0);
    if (t < SCAN_BLOCKS) g_bsum[t] = excl;
}

// scan3: add block offsets; init cursor; rowptr[N] = E
__global__ void scan3_kernel() {
    int i = blockIdx.x * 1024 + threadIdx.x;
    if (i < N_NODES) {
        int v = g_rowptr[i] + g_bsum[blockIdx.x];
        g_rowptr[i] = v;
        g_cursor[i] = v;
    }
    if (i == 0) g_rowptr[N_NODES] = N_EDGES;
}

__global__ void fill_kernel() {
    int e = blockIdx.x * blockDim.x + threadIdx.x;
    if (e < N_EDGES) {
        int pos = atomicAdd(&g_cursor[g_ed[e]], 1);
        g_eid[pos] = g_es[e];
    }
}

// ---------------- build bf16 hi/lo weights, [j][k] K-major ----------------
__global__ void buildWb_kernel(const float* __restrict__ Wl,
                               const float* __restrict__ Wr, int layer) {
    int idx = blockIdx.x * blockDim.x + threadIdx.x;
    if (idx < D * K2) {
        int j = idx >> 8;        // 0..127
        int k = idx & 255;       // 0..255
        float w = (k < D) ? Wl[j * D + k] : Wr[j * D + (k - D)];
        __nv_bfloat16 hi = __float2bfloat16(w);
        __nv_bfloat16 lo = __float2bfloat16(w - __bfloat162float(hi));
        g_Wbh[layer][idx] = hi;
        g_Wbl[layer][idx] = lo;
    }
}

// ---------------- fused layer: gather mean -> smem, then HMMA GEMM -----------
// smem: A region 64KB (AH0@0, AL0@16K, AH1@32K, AL1@48K; chunks 2/3 reuse 0/16K)
//       B region 32KB (BH@64K, BL@80K). Total 96KB -> occupancy 2.
#define OFF_BH 65536
#define OFF_BL 81920
#define SMEM_TOT 98304

__global__ void __launch_bounds__(256, 2)
fused_layer_kernel(const float* __restrict__ hin, int layer,
                   const float* __restrict__ bias, float* __restrict__ out, int relu) {
    extern __shared__ char smem[];
    const uint32_t smem_base = smem_to_u32(smem);
    const int tid  = threadIdx.x;
    const int wid  = tid >> 5;
    const int lane = tid & 31;
    const int row0 = blockIdx.x * 128;
    const int warp_m = (wid >> 2) * 64;   // 0 | 64
    const int warp_n = (wid & 3) * 32;    // 0,32,64,96

    const __nv_bfloat16* __restrict__ Bhp = g_Wbh[layer];
    const __nv_bfloat16* __restrict__ Blp = g_Wbl[layer];

    // ---- phase 1: gather means for this CTA's 128 rows into A smem (chunks 0,1) ----
    // warp w handles local rows w*16 .. w*16+15; lane owns 4 feature cols.
    for (int nn = 0; nn < 16; nn++) {
        int r = wid * 16 + nn;
        int node = row0 + r;
        float4 acc = make_float4(0.f, 0.f, 0.f, 0.f);
        if (node < N_NODES) {
            int beg = g_rowptr[node];
            int end = g_rowptr[node + 1];
            int i = beg;
            for (; i + 3 < end; i += 4) {
                int s0 = __ldg(&g_eid[i]);
                int s1 = __ldg(&g_eid[i + 1]);
                int s2 = __ldg(&g_eid[i + 2]);
                int s3 = __ldg(&g_eid[i + 3]);
                float4 v0 = *reinterpret_cast<const float4*>(hin + (size_t)s0 * D + lane * 4);
                float4 v1 = *reinterpret_cast<const float4*>(hin + (size_t)s1 * D + lane * 4);
                float4 v2 = *reinterpret_cast<const float4*>(hin + (size_t)s2 * D + lane * 4);
                float4 v3 = *reinterpret_cast<const float4*>(hin + (size_t)s3 * D + lane * 4);
                acc.x += v0.x + v1.x + v2.x + v3.x;
                acc.y += v0.y + v1.y + v2.y + v3.y;
                acc.z += v0.z + v1.z + v2.z + v3.z;
                acc.w += v0.w + v1.w + v2.w + v3.w;
            }
            for (; i < end; i++) {
                int s = __ldg(&g_eid[i]);
                float4 v = *reinterpret_cast<const float4*>(hin + (size_t)s * D + lane * 4);
                acc.x += v.x; acc.y += v.y; acc.z += v.z; acc.w += v.w;
            }
            float inv = 1.0f / (float)max(end - beg, 1);
            acc.x *= inv; acc.y *= inv; acc.z *= inv; acc.w *= inv;
        }
        // split to bf16 hi/lo and store: lanes 0-15 -> chunk0 tile, 16-31 -> chunk1
        __nv_bfloat16 h0 = __float2bfloat16(acc.x), h1 = __float2bfloat16(acc.y);
        __nv_bfloat16 h2 = __float2bfloat16(acc.z), h3 = __float2bfloat16(acc.w);
        __nv_bfloat16 l0 = __float2bfloat16(acc.x - __bfloat162float(h0));
        __nv_bfloat16 l1 = __float2bfloat16(acc.y - __bfloat162float(h1));
        __nv_bfloat16 l2 = __float2bfloat16(acc.z - __bfloat162float(h2));
        __nv_bfloat16 l3 = __float2bfloat16(acc.w - __bfloat162float(h3));
        uint2 ph, pl;
        ph.x = ((uint32_t)__bfloat16_as_ushort(h1) << 16) | __bfloat16_as_ushort(h0);
        ph.y = ((uint32_t)__bfloat16_as_ushort(h3) << 16) | __bfloat16_as_ushort(h2);
        pl.x = ((uint32_t)__bfloat16_as_ushort(l1) << 16) | __bfloat16_as_ushort(l0);
        pl.y = ((uint32_t)__bfloat16_as_ushort(l3) << 16) | __bfloat16_as_ushort(l2);
        uint32_t cs = (uint32_t)(lane >> 4) * 32768u;
        uint32_t cg = lane & 15;
        uint32_t sw = SMEM_SWIZZLE_128B((uint32_t)(r * 128 + cg * 8));
        *reinterpret_cast<uint2*>(smem + cs + sw)          = ph;
        *reinterpret_cast<uint2*>(smem + cs + 16384 + sw)  = pl;
    }

    // ---- phase 2: HMMA over 4 K-chunks ----
    float acc[4][4][4];
#pragma unroll
    for (int mt = 0; mt < 4; mt++)
#pragma unroll
        for (int nt = 0; nt < 4; nt++)
#pragma unroll
            for (int q = 0; q < 4; q++) acc[mt][nt][q] = 0.f;

    const int a_row  = (lane & 15);
    const int a_koff = (lane >> 4) * 8;
    const int b_row  = (lane & 7) + ((lane >> 4) << 3);
    const int b_koff = ((lane >> 3) & 1) * 8;

    for (int chunk = 0; chunk < 4; chunk++) {
        // B chunk: 128 n-rows x 64 bf16 (hi & lo)
#pragma unroll
        for (int i = 0; i < 8; i++) {
            int g  = tid + i * 256;
            int r  = g >> 4;
            int c4 = g & 15;
            int k = chunk * 64 + c4 * 4;
            uint2 vh = *reinterpret_cast<const uint2*>(Bhp + (size_t)r * K2 + k);
            uint2 vl = *reinterpret_cast<const uint2*>(Blp + (size_t)r * K2 + k);
            uint32_t sw = SMEM_SWIZZLE_128B((uint32_t)(r * 128 + c4 * 8));
            *reinterpret_cast<uint2*>(smem + OFF_BH + sw) = vh;
            *reinterpret_cast<uint2*>(smem + OFF_BL + sw) = vl;
        }
        // chunks 2,3: self features from hin into reused A region (AH0/AL0)
        if (chunk >= 2) {
#pragma unroll
            for (int i = 0; i < 8; i++) {
                int g  = tid + i * 256;
                int r  = g >> 4;
                int c4 = g & 15;
                int grow = row0 + r;
                int k2 = (chunk - 2) * 64 + c4 * 4;
                float4 v = make_float4(0.f, 0.f, 0.f, 0.f);
                if (grow < N_NODES)
                    v = *reinterpret_cast<const float4*>(hin + (size_t)grow * D + k2);
                __nv_bfloat16 h0 = __float2bfloat16(v.x), h1 = __float2bfloat16(v.y);
                __nv_bfloat16 h2 = __float2bfloat16(v.z), h3 = __float2bfloat16(v.w);
                __nv_bfloat16 l0 = __float2bfloat16(v.x - __bfloat162float(h0));
                __nv_bfloat16 l1 = __float2bfloat16(v.y - __bfloat162float(h1));
                __nv_bfloat16 l2 = __float2bfloat16(v.z - __bfloat162float(h2));
                __nv_bfloat16 l3 = __float2bfloat16(v.w - __bfloat162float(h3));
                uint2 ph, pl;
                ph.x = ((uint32_t)__bfloat16_as_ushort(h1) << 16) | __bfloat16_as_ushort(h0);
                ph.y = ((uint32_t)__bfloat16_as_ushort(h3) << 16) | __bfloat16_as_ushort(h2);
                pl.x = ((uint32_t)__bfloat16_as_ushort(l1) << 16) | __bfloat16_as_ushort(l0);
                pl.y = ((uint32_t)__bfloat16_as_ushort(l3) << 16) | __bfloat16_as_ushort(l2);
                uint32_t sw = SMEM_SWIZZLE_128B((uint32_t)(r * 128 + c4 * 8));
                *reinterpret_cast<uint2*>(smem + sw)          = ph;
                *reinterpret_cast<uint2*>(smem + 16384 + sw)  = pl;
            }
        }
        __syncthreads();

        const uint32_t offAH = (chunk == 1) ? 32768u : 0u;
        const uint32_t offAL = offAH + 16384u;

#pragma unroll
        for (int ks = 0; ks < 4; ks++) {
            uint32_t bh[2][4], blo[2][4];
#pragma unroll
            for (int np = 0; np < 2; np++) {
                uint32_t off = SMEM_SWIZZLE_128B(
                    (uint32_t)((warp_n + np * 16 + b_row) * 128 + (ks * 16 + b_koff) * 2));
                LDMATRIX_X4(bh[np][0], bh[np][1], bh[np][2], bh[np][3],
                            smem_base + OFF_BH + off);
                LDMATRIX_X4(blo[np][0], blo[np][1], blo[np][2], blo[np][3],
                            smem_base + OFF_BL + off);
            }
            uint32_t a[4][4];
#pragma unroll
            for (int mt = 0; mt < 4; mt++) {
                uint32_t off = SMEM_SWIZZLE_128B(
                    (uint32_t)((warp_m + mt * 16 + a_row) * 128 + (ks * 16 + a_koff) * 2));
                LDMATRIX_X4(a[mt][0], a[mt][1], a[mt][2], a[mt][3],
                            smem_base + offAH + off);
            }
#pragma unroll
            for (int mt = 0; mt < 4; mt++)
#pragma unroll
                for (int nt = 0; nt < 4; nt++) {
                    int np = nt >> 1, hf = nt & 1;
                    MMA_BF16(acc[mt][nt][0], acc[mt][nt][1], acc[mt][nt][2], acc[mt][nt][3],
                             a[mt][0], a[mt][1], a[mt][2], a[mt][3],
                             bh[np][hf * 2], bh[np][hf * 2 + 1]);
                    MMA_BF16(acc[mt][nt][0], acc[mt][nt][1], acc[mt][nt][2], acc[mt][nt][3],
                             a[mt][0], a[mt][1], a[mt][2], a[mt][3],
                             blo[np][hf * 2], blo[np][hf * 2 + 1]);
                }
#pragma unroll
            for (int mt = 0; mt < 4; mt++) {
                uint32_t off = SMEM_SWIZZLE_128B(
                    (uint32_t)((warp_m + mt * 16 + a_row) * 128 + (ks * 16 + a_koff) * 2));
                LDMATRIX_X4(a[mt][0], a[mt][1], a[mt][2], a[mt][3],
                            smem_base + offAL + off);
            }
#pragma unroll
            for (int mt = 0; mt < 4; mt++)
#pragma unroll
                for (int nt = 0; nt < 4; nt++) {
                    int np = nt >> 1, hf = nt & 1;
                    MMA_BF16(acc[mt][nt][0], acc[mt][nt][1], acc[mt][nt][2], acc[mt][nt][3],
                             a[mt][0], a[mt][1], a[mt][2], a[mt][3],
                             bh[np][hf * 2], bh[np][hf * 2 + 1]);
                }
        }
        __syncthreads();
    }

    // ---- epilogue: bias (+relu), store fp32 ----
    const int gid = lane >> 2;
    const int tig = lane & 3;
#pragma unroll
    for (int mt = 0; mt < 4; mt++) {
        int r_base = row0 + warp_m + mt * 16 + gid;
#pragma unroll
        for (int nt = 0; nt < 4; nt++) {
            int j = warp_n + nt * 8 + tig * 2;
            float b0 = __ldg(&bias[j]), b1 = __ldg(&bias[j + 1]);
            float2 v0, v1;
            v0.x = acc[mt][nt][0] + b0; v0.y = acc[mt][nt][1] + b1;
            v1.x = acc[mt][nt][2] + b0; v1.y = acc[mt][nt][3] + b1;
            if (relu) {
                v0.x = fmaxf(v0.x, 0.f); v0.y = fmaxf(v0.y, 0.f);
                v1.x = fmaxf(v1.x, 0.f); v1.y = fmaxf(v1.y, 0.f);
            }
            if (r_base < N_NODES)
                *reinterpret_cast<float2*>(out + (size_t)r_base * D + j) = v0;
            if (r_base + 8 < N_NODES)
                *reinterpret_cast<float2*>(out + (size_t)(r_base + 8) * D + j) = v1;
        }
    }
}

// ---------------- launch ----------------
extern "C" void kernel_launch(void* const* d_in, const int* in_sizes, int n_in,
                              void* d_out, int out_size) {
    const float* x     = (const float*)d_in[0];
    const int*   e32   = (const int*)d_in[1];
    const float* Wl[4] = {(const float*)d_in[2],  (const float*)d_in[5],
                          (const float*)d_in[8],  (const float*)d_in[11]};
    const float* bl[4] = {(const float*)d_in[3],  (const float*)d_in[6],
                          (const float*)d_in[9],  (const float*)d_in[12]};
    const float* Wr[4] = {(const float*)d_in[4],  (const float*)d_in[7],
                          (const float*)d_in[10], (const float*)d_in[13]};
    float* out = (float*)d_out;

    float* h0 = nullptr; float* h1 = nullptr;
    cudaGetSymbolAddress((void**)&h0, g_h0);
    cudaGetSymbolAddress((void**)&h1, g_h1);

    cudaFuncSetAttribute(fused_layer_kernel,
                         cudaFuncAttributeMaxDynamicSharedMemorySize, SMEM_TOT);

    // decode edges + CSR build + weight prep
    detect_kernel<<<1, 32>>>(e32);
    decode_kernel<<<(2 * N_EDGES + 255) / 256, 256>>>(e32);
    zero_deg_kernel<<<(N_NODES + 255) / 256, 256>>>();
    count_kernel<<<(N_EDGES + 255) / 256, 256>>>();
    scan1_kernel<<<SCAN_BLOCKS, 1024>>>();
    scan2_kernel<<<1, 64>>>();
    scan3_kernel<<<SCAN_BLOCKS, 1024>>>();
    fill_kernel<<<(N_EDGES + 255) / 256, 256>>>();
    for (int l = 0; l < 4; l++)
        buildWb_kernel<<<(D * K2 + 255) / 256, 256>>>(Wl[l], Wr[l], l);

    const float* hin[4]  = {x,  h0, h1, h0};
    float*       hout[4] = {h0, h1, h0, out};

    const int layer_blocks = (N_NODES + 127) / 128;   // 391

    for (int l = 0; l < 4; l++)
        fused_layer_kernel<<<layer_blocks, 256, SMEM_TOT>>>(hin[l], l, bl[l], hout[l],
                                                            l == 0 ? 1 : 0);
}